// round 9
// baseline (speedup 1.0000x reference)
#include <cuda_runtime.h>
#include <cstdint>

#define NBLK 152
#define TPB  768
#define B_N  4096
#define D_N  3072
#define C_N  10
#define MAXR 27
#define NW   (TPB / 32)
#define RPT  3
#define STG  4
#define TILE_FLOATS (RPT * D_N)
#define TILE_BYTES  (TILE_FLOATS * 4)
#define DYN_SMEM    (STG * TILE_BYTES)
#define R0BLK 23
#define REMROWS (B_N - R0BLK)
#define NB1 (NBLK - 1)

typedef unsigned long long ull;

__device__ float g_M[C_N * C_N];
__device__ float g_partial[NBLK];
__device__ unsigned int g_ticket;
__device__ unsigned int g_mflag;

__device__ __forceinline__ uint32_t smem_u32(const void* p) {
    uint32_t a;
    asm("{ .reg .u64 t; cvta.to.shared.u64 t, %1; cvt.u32.u64 %0, t; }" : "=r"(a) : "l"(p));
    return a;
}
__device__ __forceinline__ void mbar_init(uint32_t addr, uint32_t cnt) {
    asm volatile("mbarrier.init.shared.b64 [%0], %1;" :: "r"(addr), "r"(cnt) : "memory");
}
__device__ __forceinline__ void mbar_expect_tx(uint32_t addr, uint32_t bytes) {
    asm volatile("mbarrier.arrive.expect_tx.shared.b64 _, [%0], %1;" :: "r"(addr), "r"(bytes) : "memory");
}
__device__ __forceinline__ void bulk_g2s(uint32_t dst, const void* src, uint32_t bytes, uint32_t mbar) {
    asm volatile("cp.async.bulk.shared::cta.global.mbarrier::complete_tx::bytes [%0], [%1], %2, [%3];"
                 :: "r"(dst), "l"(src), "r"(bytes), "r"(mbar) : "memory");
}
__device__ __forceinline__ void mbar_wait(uint32_t addr, uint32_t parity) {
    uint32_t done;
    asm volatile(
        "{\n\t.reg .pred p;\n\t"
        "mbarrier.try_wait.parity.shared.b64 p, [%1], %2;\n\t"
        "selp.b32 %0, 1, 0, p;\n\t}"
        : "=r"(done) : "r"(addr), "r"(parity) : "memory");
    if (!done) {
        asm volatile(
            "{\n\t.reg .pred P1;\n\t"
            "WL_%=:\n\t"
            "mbarrier.try_wait.parity.shared.b64 P1, [%0], %1, 0x989680;\n\t"
            "@P1 bra.uni WD_%=;\n\t"
            "bra.uni WL_%=;\n\t"
            "WD_%=:\n\t}"
            :: "r"(addr), "r"(parity) : "memory");
    }
}

// One row: 2 ull x-pairs from smem feed f32x2 FMA directly; 17-SHFL value-split reduce.
__device__ __forceinline__ void do_row(const ull* __restrict__ row, int tid, int warp, int lane,
                                       const ull (&wp)[2][C_N],
                                       float (*sp)[NW][C_N], int r) {
    ull x0 = row[tid];
    ull x1 = row[tid + TPB];
    ull acc[C_N];
#pragma unroll
    for (int k = 0; k < C_N; k++) acc[k] = 0ull;
#pragma unroll
    for (int k = 0; k < C_N; k++)
        asm("fma.rn.f32x2 %0, %1, %2, %0;" : "+l"(acc[k]) : "l"(x0), "l"(wp[0][k]));
#pragma unroll
    for (int k = 0; k < C_N; k++)
        asm("fma.rn.f32x2 %0, %1, %2, %0;" : "+l"(acc[k]) : "l"(x1), "l"(wp[1][k]));

    float z[C_N];
#pragma unroll
    for (int k = 0; k < C_N; k++) {
        float lo, hi;
        asm("mov.b64 {%0, %1}, %2;" : "=f"(lo), "=f"(hi) : "l"(acc[k]));
        z[k] = lo + hi;
    }

    // Value-splitting reduction: 10 -> 5 (xor16), 5 -> 3 (xor8), then 3x3 naive
    const bool hi16 = (lane & 16) != 0;
    const bool hi8  = (lane & 8) != 0;
    float v[5];
#pragma unroll
    for (int j = 0; j < 5; j++) {
        float send = hi16 ? z[j] : z[j + 5];
        float oth = __shfl_xor_sync(0xffffffffu, send, 16);
        v[j] = (hi16 ? z[j + 5] : z[j]) + oth;
    }
    float u[3];
#pragma unroll
    for (int j = 0; j < 3; j++) {
        float mine = (j < 2) ? v[j + 3] : 0.f;
        float send = hi8 ? v[j] : mine;
        float oth = __shfl_xor_sync(0xffffffffu, send, 8);
        u[j] = (hi8 ? mine : v[j]) + oth;
    }
#pragma unroll
    for (int off = 4; off; off >>= 1)
#pragma unroll
        for (int j = 0; j < 3; j++)
            u[j] += __shfl_xor_sync(0xffffffffu, u[j], off);

    if ((lane & 7) == 0) {
        int vb = (hi16 ? 5 : 0) + (hi8 ? 3 : 0);
        int c = hi8 ? 2 : 3;
#pragma unroll
        for (int j = 0; j < 3; j++)
            if (j < c) sp[r][warp][vb + j] = u[j];
    }
}

__global__ void __launch_bounds__(TPB, 1) jacreg_kernel(
        const float* __restrict__ X, const float* __restrict__ W,
        float* __restrict__ out) {
    extern __shared__ float tiles[];
    __shared__ float sM[C_N * C_N];
    __shared__ float sp[MAXR][NW][C_N];
    __shared__ float redM[NW][56];
    __shared__ ull mbar[STG];
    __shared__ int slast;

    const int tid = threadIdx.x, b = blockIdx.x;
    const int warp = tid >> 5, lane = tid & 31;
    int r0, r1;
    if (b == 0) { r0 = 0; r1 = R0BLK; }
    else {
        r0 = R0BLK + (int)(((long long)(b - 1) * REMROWS) / NB1);
        r1 = R0BLK + (int)(((long long)b * REMROWS) / NB1);
    }
    const int nrows = r1 - r0;
    const int ntiles = (nrows + RPT - 1) / RPT;

    // W packed as adjacent-d pairs: wp[j][k] = (W[e][k], W[e+1][k]), e = (j*TPB+tid)*2
    ull wp[2][C_N];
#pragma unroll
    for (int j = 0; j < 2; j++) {
        int e = (j * TPB + tid) * 2;
        const float* w0 = W + (size_t)e * C_N;
        const float* w1 = w0 + C_N;
#pragma unroll
        for (int k = 0; k < C_N; k++) {
            float a = __ldg(w0 + k), bb = __ldg(w1 + k);
            asm("mov.b64 %0, {%1, %2};" : "=l"(wp[j][k]) : "f"(a), "f"(bb));
        }
    }

    uint32_t mbar_a = smem_u32(&mbar[0]);
    uint32_t tile_a = smem_u32(&tiles[0]);

    if (tid == 0) {
#pragma unroll
        for (int s = 0; s < STG; s++) mbar_init(mbar_a + 8 * s, 1);
        asm volatile("fence.proxy.async.shared::cta;" ::: "memory");
    }
    __syncthreads();

    // Prologue: fill stages (overlaps block0's M computation)
    if (tid == 0) {
        int np = (ntiles < STG) ? ntiles : STG;
        for (int t = 0; t < np; t++) {
            int rbase = t * RPT;
            int cnt = nrows - rbase; if (cnt > RPT) cnt = RPT;
            uint32_t bytes = (uint32_t)cnt * D_N * 4;
            mbar_expect_tx(mbar_a + 8 * t, bytes);
            bulk_g2s(tile_a + t * TILE_BYTES,
                     X + (size_t)(r0 + rbase) * D_N, bytes, mbar_a + 8 * t);
        }
    }

    // Block 0: M = W^T W from wp registers; publish with release flag
    if (b == 0) {
        float w[4][C_N];
#pragma unroll
        for (int j = 0; j < 2; j++)
#pragma unroll
            for (int k = 0; k < C_N; k++)
                asm("mov.b64 {%0, %1}, %2;"
                    : "=f"(w[2 * j][k]), "=f"(w[2 * j + 1][k]) : "l"(wp[j][k]));
        int idx = 0;
#pragma unroll
        for (int k = 0; k < C_N; k++) {
            float a[C_N];
#pragma unroll
            for (int l = k; l < C_N; l++) {
                float s = 0.f;
#pragma unroll
                for (int pos = 0; pos < 4; pos++) s += w[pos][k] * w[pos][l];
                a[l - k] = s;
            }
#pragma unroll
            for (int off = 16; off; off >>= 1)
#pragma unroll
                for (int t = 0; t < C_N - k; t++)
                    a[t] += __shfl_xor_sync(0xffffffffu, a[t], off);
            if (lane == 0)
#pragma unroll
                for (int t = 0; t < C_N - k; t++) redM[warp][idx + t] = a[t];
            idx += C_N - k;
        }
        __syncthreads();
        if (tid < 55) {
            float s = 0.f;
#pragma unroll
            for (int wv = 0; wv < NW; wv++) s += redM[wv][tid];
            int k = 0, t = tid;
            while (t >= C_N - k) { t -= C_N - k; k++; }
            int l = k + t;
            g_M[k * C_N + l] = s;
            g_M[l * C_N + k] = s;
        }
        __syncthreads();
        if (tid == 0) {
            __threadfence();
            *(volatile unsigned int*)&g_mflag = 1u;
        }
    }

    // -------- Phase A: paired tiles (one barrier per 2 tiles) --------
    for (int t = 0; t < ntiles; t += 2) {
        {
            int s = t & (STG - 1);
            mbar_wait(mbar_a + 8 * s, (t / STG) & 1);
            int rbase = t * RPT;
            int cnt = nrows - rbase; if (cnt > RPT) cnt = RPT;
            const ull* tile = (const ull*)(tiles + s * TILE_FLOATS);
            for (int rl = 0; rl < cnt; rl++)
                do_row(tile + rl * (D_N / 2), tid, warp, lane, wp, sp, rbase + rl);
        }
        if (t + 1 < ntiles) {
            int s = (t + 1) & (STG - 1);
            mbar_wait(mbar_a + 8 * s, ((t + 1) / STG) & 1);
            int rbase = (t + 1) * RPT;
            int cnt = nrows - rbase; if (cnt > RPT) cnt = RPT;
            const ull* tile = (const ull*)(tiles + s * TILE_FLOATS);
            for (int rl = 0; rl < cnt; rl++)
                do_row(tile + rl * (D_N / 2), tid, warp, lane, wp, sp, rbase + rl);
        }
        __syncthreads();   // reads of both stages done
        if (tid == 0) {
#pragma unroll
            for (int d = 0; d < 2; d++) {
                int tt = t + STG + d;
                if (tt < ntiles) {
                    int rb = tt * RPT;
                    int c = nrows - rb; if (c > RPT) c = RPT;
                    uint32_t bytes = (uint32_t)c * D_N * 4;
                    int s = tt & (STG - 1);
                    mbar_expect_tx(mbar_a + 8 * s, bytes);
                    bulk_g2s(tile_a + s * TILE_BYTES,
                             X + (size_t)(r0 + rb) * D_N, bytes, mbar_a + 8 * s);
                }
            }
        }
    }

    // Acquire M (block0 published long ago)
    if (tid == 0) {
        volatile unsigned int* vf = &g_mflag;
        while (*vf == 0u) {}
        __threadfence();
    }
    __syncthreads();
    if (tid < C_N * C_N) sM[tid] = g_M[tid];
    __syncthreads();

    // -------- Phase B: one thread per row --------
    float myreg = 0.f;
    if (tid < nrows) {
        float z[C_N];
#pragma unroll
        for (int k = 0; k < C_N; k++) {
            float s = 0.f;
#pragma unroll
            for (int wv = 0; wv < NW; wv++) s += sp[tid][wv][k];
            z[k] = s;
        }
        float zmax = z[0];
#pragma unroll
        for (int k = 1; k < C_N; k++) zmax = fmaxf(zmax, z[k]);
        float q[C_N], qs = 0.f;
#pragma unroll
        for (int k = 0; k < C_N; k++) { q[k] = __expf(z[k] - zmax); qs += q[k]; }
        float inv = 1.f / qs;
#pragma unroll
        for (int k = 0; k < C_N; k++) q[k] *= inv;

        const float A = 1.0f - (float)C_N * 1e-6f;
        float p[C_N], sq[C_N];
#pragma unroll
        for (int k = 0; k < C_N; k++) { p[k] = q[k] * A + 1e-6f; sq[k] = sqrtf(p[k]); }
        float sm = sq[C_N - 1], qm = q[C_N - 1];
        float om = 1.f - sm;

        float uu[C_N], Qf = 0.f;
#pragma unroll
        for (int k = 0; k < C_N; k++) {
            float t = 0.f;
#pragma unroll
            for (int l = 0; l < C_N; l++) t += sM[k * C_N + l] * q[l];
            uu[k] = t;
            Qf += q[k] * t;
        }

        float jac2 = 0.f;
        float bfac = A * qm / (sm * om * om);
#pragma unroll
        for (int i = 0; i < C_N - 1; i++) {
            float al = A * q[i] / (sq[i] * om);
            float be = sq[i] * bfac;
            float ga = al + be;
            jac2 += al * al * sM[i * C_N + i]
                  + be * be * sM[C_N * C_N - 1]
                  + ga * ga * Qf
                  + 2.f * al * be * sM[i * C_N + (C_N - 1)]
                  - 2.f * al * ga * uu[i]
                  - 2.f * be * ga * uu[C_N - 1];
        }
        float jn = sqrtf(jac2);

        float ssum = 0.f;
#pragma unroll
        for (int k = 0; k < C_N; k++) ssum += sq[k];
        float arg = ssum * 0.316227766016838f;
        arg = fminf(fmaxf(arg, -1.f), 1.f);
        float delta = 2.f * acosf(arg);

        float psum = 0.f;
#pragma unroll
        for (int k = 0; k < C_N - 1; k++) psum += p[k];
        float rho = (2.f * om - psum) / om;

        float xv = jn - delta / (rho * 0.1f);
        myreg = (xv > 0.f) ? xv : expm1f(xv);
    }

    if (warp == 0) {
#pragma unroll
        for (int off = 16; off; off >>= 1)
            myreg += __shfl_xor_sync(0xffffffffu, myreg, off);
        if (lane == 0) {
            g_partial[b] = myreg;
            __threadfence();
            unsigned int rank = atomicAdd(&g_ticket, 1u);
            slast = (rank == NBLK - 1) ? 1 : 0;
            if (rank == NBLK - 1) {
                g_ticket = 0u;
                g_mflag = 0u;
            }
        }
    }
    __syncthreads();

    if (slast && warp == 0) {
        float s = 0.f;
        for (int i = lane; i < NBLK; i += 32) s += __ldcg(&g_partial[i]);
#pragma unroll
        for (int off = 16; off; off >>= 1)
            s += __shfl_xor_sync(0xffffffffu, s, off);
        if (lane == 0) out[0] = s * (1.f / (float)B_N);
    }
}

extern "C" void kernel_launch(void* const* d_in, const int* in_sizes, int n_in,
                              void* d_out, int out_size) {
    const float* X = (const float*)d_in[0];
    const float* W = (const float*)d_in[1];
    float* out = (float*)d_out;
    cudaFuncSetAttribute(jacreg_kernel,
                         cudaFuncAttributeMaxDynamicSharedMemorySize, DYN_SMEM);
    jacreg_kernel<<<NBLK, TPB, DYN_SMEM>>>(X, W, out);
}

// round 11
// speedup vs baseline: 1.2807x; 1.2807x over previous
#include <cuda_runtime.h>
#include <cstdint>

#define NBLK 152
#define TPB  512
#define B_N  4096
#define D_N  3072
#define C_N  10
#define MAXR 27
#define NW   (TPB / 32)
#define RPT  3
#define STG  4
#define TILE_FLOATS (RPT * D_N)
#define TILE_BYTES  (TILE_FLOATS * 4)
#define DYN_SMEM    (STG * TILE_BYTES)
#define R0BLK 23
#define REMROWS (B_N - R0BLK)
#define NB1 (NBLK - 1)

typedef unsigned long long ull;

__device__ float g_M[C_N * C_N];
__device__ float g_partial[NBLK];
__device__ unsigned int g_ticket;
__device__ unsigned int g_mflag;

__device__ __forceinline__ uint32_t smem_u32(const void* p) {
    uint32_t a;
    asm("{ .reg .u64 t; cvta.to.shared.u64 t, %1; cvt.u32.u64 %0, t; }" : "=r"(a) : "l"(p));
    return a;
}
__device__ __forceinline__ void mbar_init(uint32_t addr, uint32_t cnt) {
    asm volatile("mbarrier.init.shared.b64 [%0], %1;" :: "r"(addr), "r"(cnt) : "memory");
}
__device__ __forceinline__ void mbar_expect_tx(uint32_t addr, uint32_t bytes) {
    asm volatile("mbarrier.arrive.expect_tx.shared.b64 _, [%0], %1;" :: "r"(addr), "r"(bytes) : "memory");
}
__device__ __forceinline__ void mbar_arrive(uint32_t addr) {
    asm volatile("mbarrier.arrive.shared.b64 _, [%0];" :: "r"(addr) : "memory");
}
__device__ __forceinline__ void bulk_g2s(uint32_t dst, const void* src, uint32_t bytes, uint32_t mbar) {
    asm volatile("cp.async.bulk.shared::cta.global.mbarrier::complete_tx::bytes [%0], [%1], %2, [%3];"
                 :: "r"(dst), "l"(src), "r"(bytes), "r"(mbar) : "memory");
}
__device__ __forceinline__ void mbar_wait(uint32_t addr, uint32_t parity) {
    uint32_t done;
    asm volatile(
        "{\n\t.reg .pred p;\n\t"
        "mbarrier.try_wait.parity.shared.b64 p, [%1], %2;\n\t"
        "selp.b32 %0, 1, 0, p;\n\t}"
        : "=r"(done) : "r"(addr), "r"(parity) : "memory");
    if (!done) {
        asm volatile(
            "{\n\t.reg .pred P1;\n\t"
            "WL_%=:\n\t"
            "mbarrier.try_wait.parity.shared.b64 P1, [%0], %1, 0x989680;\n\t"
            "@P1 bra.uni WD_%=;\n\t"
            "bra.uni WL_%=;\n\t"
            "WD_%=:\n\t}"
            :: "r"(addr), "r"(parity) : "memory");
    }
}

// One row (R3's best body): float2 loads, broadcast f32x2 FMA, 17-SHFL value-split reduce.
__device__ __forceinline__ void do_row(const float2* __restrict__ row, int tid, int warp, int lane,
                                       const ull (&wp)[3][2][5],
                                       float (*sp)[NW][C_N], int r) {
    float2 x0 = row[tid];
    float2 x1 = row[tid + TPB];
    float2 x2 = row[tid + 2 * TPB];

    ull acc[5];
#pragma unroll
    for (int m = 0; m < 5; m++) acc[m] = 0ull;
#pragma unroll
    for (int j = 0; j < 3; j++)
#pragma unroll
        for (int c2 = 0; c2 < 2; c2++) {
            float xv = (j == 0) ? (c2 == 0 ? x0.x : x0.y)
                     : (j == 1) ? (c2 == 0 ? x1.x : x1.y)
                                : (c2 == 0 ? x2.x : x2.y);
            ull xb;
            asm("mov.b64 %0, {%1, %1};" : "=l"(xb) : "f"(xv));
#pragma unroll
            for (int m = 0; m < 5; m++)
                asm("fma.rn.f32x2 %0, %1, %2, %0;"
                    : "+l"(acc[m]) : "l"(xb), "l"(wp[j][c2][m]));
        }

    float z[C_N];
#pragma unroll
    for (int m = 0; m < 5; m++)
        asm("mov.b64 {%0, %1}, %2;" : "=f"(z[2*m]), "=f"(z[2*m+1]) : "l"(acc[m]));

    const bool hi16 = (lane & 16) != 0;
    const bool hi8  = (lane & 8) != 0;
    float v[5];
#pragma unroll
    for (int j = 0; j < 5; j++) {
        float send = hi16 ? z[j] : z[j + 5];
        float oth = __shfl_xor_sync(0xffffffffu, send, 16);
        v[j] = (hi16 ? z[j + 5] : z[j]) + oth;
    }
    float u[3];
#pragma unroll
    for (int j = 0; j < 3; j++) {
        float mine = (j < 2) ? v[j + 3] : 0.f;
        float send = hi8 ? v[j] : mine;
        float oth = __shfl_xor_sync(0xffffffffu, send, 8);
        u[j] = (hi8 ? mine : v[j]) + oth;
    }
#pragma unroll
    for (int off = 4; off; off >>= 1)
#pragma unroll
        for (int j = 0; j < 3; j++)
            u[j] += __shfl_xor_sync(0xffffffffu, u[j], off);

    if ((lane & 7) == 0) {
        int vb = (hi16 ? 5 : 0) + (hi8 ? 3 : 0);
        int c = hi8 ? 2 : 3;
#pragma unroll
        for (int j = 0; j < 3; j++)
            if (j < c) sp[r][warp][vb + j] = u[j];
    }
}

__global__ void __launch_bounds__(TPB, 1) jacreg_kernel(
        const float* __restrict__ X, const float* __restrict__ W,
        float* __restrict__ out) {
    extern __shared__ float tiles[];
    __shared__ float sM[C_N * C_N];
    __shared__ float sp[MAXR][NW][C_N];
    __shared__ float redM[NW][56];
    __shared__ ull mb_full[STG];
    __shared__ ull mb_cons[STG];
    __shared__ int slast;

    const int tid = threadIdx.x, b = blockIdx.x;
    const int warp = tid >> 5, lane = tid & 31;
    int r0, r1;
    if (b == 0) { r0 = 0; r1 = R0BLK; }
    else {
        r0 = R0BLK + (int)(((long long)(b - 1) * REMROWS) / NB1);
        r1 = R0BLK + (int)(((long long)b * REMROWS) / NB1);
    }
    const int nrows = r1 - r0;
    const int ntiles = (nrows + RPT - 1) / RPT;

    // W packed into f32x2 class-pairs: thread owns 6 D-positions e = (j*TPB+tid)*2+c2
    ull wp[3][2][5];
#pragma unroll
    for (int j = 0; j < 3; j++)
#pragma unroll
        for (int c2 = 0; c2 < 2; c2++) {
            int e = (j * TPB + tid) * 2 + c2;
            const ull* wrow = (const ull*)(W + (size_t)e * C_N);
#pragma unroll
            for (int m = 0; m < 5; m++) wp[j][c2][m] = wrow[m];
        }

    uint32_t full_a = smem_u32(&mb_full[0]);
    uint32_t cons_a = smem_u32(&mb_cons[0]);
    uint32_t tile_a = smem_u32(&tiles[0]);

    if (tid == 0) {
#pragma unroll
        for (int s = 0; s < STG; s++) {
            mbar_init(full_a + 8 * s, 1);
            mbar_init(cons_a + 8 * s, NW);
        }
        asm volatile("fence.proxy.async.shared::cta;" ::: "memory");
    }
    __syncthreads();

    // Prologue: fill all stages
    if (tid == 0) {
        int np = (ntiles < STG) ? ntiles : STG;
        for (int t = 0; t < np; t++) {
            int rbase = t * RPT;
            int cnt = nrows - rbase; if (cnt > RPT) cnt = RPT;
            uint32_t bytes = (uint32_t)cnt * D_N * 4;
            mbar_expect_tx(full_a + 8 * t, bytes);
            bulk_g2s(tile_a + t * TILE_BYTES,
                     X + (size_t)(r0 + rbase) * D_N, bytes, full_a + 8 * t);
        }
    }

    // Block 0: M = W^T W from wp registers; publish with release flag
    if (b == 0) {
        float w[6][C_N];
#pragma unroll
        for (int j = 0; j < 3; j++)
#pragma unroll
            for (int c2 = 0; c2 < 2; c2++)
#pragma unroll
                for (int m = 0; m < 5; m++)
                    asm("mov.b64 {%0, %1}, %2;"
                        : "=f"(w[j * 2 + c2][2 * m]), "=f"(w[j * 2 + c2][2 * m + 1])
                        : "l"(wp[j][c2][m]));
        int idx = 0;
#pragma unroll
        for (int k = 0; k < C_N; k++) {
            float a[C_N];
#pragma unroll
            for (int l = k; l < C_N; l++) {
                float s = 0.f;
#pragma unroll
                for (int pos = 0; pos < 6; pos++) s += w[pos][k] * w[pos][l];
                a[l - k] = s;
            }
#pragma unroll
            for (int off = 16; off; off >>= 1)
#pragma unroll
                for (int t = 0; t < C_N - k; t++)
                    a[t] += __shfl_xor_sync(0xffffffffu, a[t], off);
            if (lane == 0)
#pragma unroll
                for (int t = 0; t < C_N - k; t++) redM[warp][idx + t] = a[t];
            idx += C_N - k;
        }
        __syncthreads();
        if (tid < 55) {
            float s = 0.f;
#pragma unroll
            for (int wv = 0; wv < NW; wv++) s += redM[wv][tid];
            int k = 0, t = tid;
            while (t >= C_N - k) { t -= C_N - k; k++; }
            int l = k + t;
            g_M[k * C_N + l] = s;
            g_M[l * C_N + k] = s;
        }
        __syncthreads();
        if (tid == 0) {
            __threadfence();
            *(volatile unsigned int*)&g_mflag = 1u;
        }
    }

    // -------- Phase A: producer-consumer, NO block barrier; warps drift freely --------
    for (int t = 0; t < ntiles; t++) {
        int s = t & (STG - 1);
        uint32_t par = (t >> 2) & 1;
        mbar_wait(full_a + 8 * s, par);

        int rbase = t * RPT;
        int cnt = nrows - rbase; if (cnt > RPT) cnt = RPT;
        const float2* tile = (const float2*)(tiles + s * TILE_FLOATS);
        for (int rl = 0; rl < cnt; rl++)
            do_row(tile + rl * (D_N / 2), tid, warp, lane, wp, sp, rbase + rl);

        if (lane == 0) mbar_arrive(cons_a + 8 * s);   // this warp done with stage s

        if (warp == 0) {
            int tt = t + STG;
            if (tt < ntiles) {
                // wait until ALL warps consumed this use of stage s, then refill
                mbar_wait(cons_a + 8 * s, par);
                if (lane == 0) {
                    int rb = tt * RPT;
                    int c = nrows - rb; if (c > RPT) c = RPT;
                    uint32_t bytes = (uint32_t)c * D_N * 4;
                    mbar_expect_tx(full_a + 8 * s, bytes);
                    bulk_g2s(tile_a + s * TILE_BYTES,
                             X + (size_t)(r0 + rb) * D_N, bytes, full_a + 8 * s);
                }
            }
        }
    }

    // Acquire M (block0 published long ago)
    if (tid == 0) {
        volatile unsigned int* vf = &g_mflag;
        while (*vf == 0u) {}
        __threadfence();
    }
    __syncthreads();
    if (tid < C_N * C_N) sM[tid] = g_M[tid];
    __syncthreads();

    // -------- Phase B: one thread per row --------
    float myreg = 0.f;
    if (tid < nrows) {
        float z[C_N];
#pragma unroll
        for (int k = 0; k < C_N; k++) {
            float s = 0.f;
#pragma unroll
            for (int wv = 0; wv < NW; wv++) s += sp[tid][wv][k];
            z[k] = s;
        }
        float zmax = z[0];
#pragma unroll
        for (int k = 1; k < C_N; k++) zmax = fmaxf(zmax, z[k]);
        float q[C_N], qs = 0.f;
#pragma unroll
        for (int k = 0; k < C_N; k++) { q[k] = __expf(z[k] - zmax); qs += q[k]; }
        float inv = 1.f / qs;
#pragma unroll
        for (int k = 0; k < C_N; k++) q[k] *= inv;

        const float A = 1.0f - (float)C_N * 1e-6f;
        float p[C_N], sq[C_N];
#pragma unroll
        for (int k = 0; k < C_N; k++) { p[k] = q[k] * A + 1e-6f; sq[k] = sqrtf(p[k]); }
        float sm = sq[C_N - 1], qm = q[C_N - 1];
        float om = 1.f - sm;

        float uu[C_N], Qf = 0.f;
#pragma unroll
        for (int k = 0; k < C_N; k++) {
            float t = 0.f;
#pragma unroll
            for (int l = 0; l < C_N; l++) t += sM[k * C_N + l] * q[l];
            uu[k] = t;
            Qf += q[k] * t;
        }

        float jac2 = 0.f;
        float bfac = A * qm / (sm * om * om);
#pragma unroll
        for (int i = 0; i < C_N - 1; i++) {
            float al = A * q[i] / (sq[i] * om);
            float be = sq[i] * bfac;
            float ga = al + be;
            jac2 += al * al * sM[i * C_N + i]
                  + be * be * sM[C_N * C_N - 1]
                  + ga * ga * Qf
                  + 2.f * al * be * sM[i * C_N + (C_N - 1)]
                  - 2.f * al * ga * uu[i]
                  - 2.f * be * ga * uu[C_N - 1];
        }
        float jn = sqrtf(jac2);

        float ssum = 0.f;
#pragma unroll
        for (int k = 0; k < C_N; k++) ssum += sq[k];
        float arg = ssum * 0.316227766016838f;
        arg = fminf(fmaxf(arg, -1.f), 1.f);
        float delta = 2.f * acosf(arg);

        float psum = 0.f;
#pragma unroll
        for (int k = 0; k < C_N - 1; k++) psum += p[k];
        float rho = (2.f * om - psum) / om;

        float xv = jn - delta / (rho * 0.1f);
        myreg = (xv > 0.f) ? xv : expm1f(xv);
    }

    if (warp == 0) {
#pragma unroll
        for (int off = 16; off; off >>= 1)
            myreg += __shfl_xor_sync(0xffffffffu, myreg, off);
        if (lane == 0) {
            g_partial[b] = myreg;
            __threadfence();
            unsigned int rank = atomicAdd(&g_ticket, 1u);
            slast = (rank == NBLK - 1) ? 1 : 0;
            if (rank == NBLK - 1) {
                g_ticket = 0u;
                g_mflag = 0u;
            }
        }
    }
    __syncthreads();

    if (slast && warp == 0) {
        float s = 0.f;
        for (int i = lane; i < NBLK; i += 32) s += __ldcg(&g_partial[i]);
#pragma unroll
        for (int off = 16; off; off >>= 1)
            s += __shfl_xor_sync(0xffffffffu, s, off);
        if (lane == 0) out[0] = s * (1.f / (float)B_N);
    }
}

extern "C" void kernel_launch(void* const* d_in, const int* in_sizes, int n_in,
                              void* d_out, int out_size) {
    const float* X = (const float*)d_in[0];
    const float* W = (const float*)d_in[1];
    float* out = (float*)d_out;
    cudaFuncSetAttribute(jacreg_kernel,
                         cudaFuncAttributeMaxDynamicSharedMemorySize, DYN_SMEM);
    jacreg_kernel<<<NBLK, TPB, DYN_SMEM>>>(X, W, out);
}

// round 12
// speedup vs baseline: 1.3173x; 1.0286x over previous
#include <cuda_runtime.h>
#include <cstdint>

#define NBLK 152
#define TPB  512
#define B_N  4096
#define D_N  3072
#define C_N  10
#define MAXR 27
#define NW   (TPB / 32)
#define RPT  4
#define STG  3
#define TILE_FLOATS (RPT * D_N)
#define TILE_BYTES  (TILE_FLOATS * 4)
#define DYN_SMEM    (STG * TILE_BYTES)
#define R0BLK 23
#define REMROWS (B_N - R0BLK)
#define NB1 (NBLK - 1)

typedef unsigned long long ull;

__device__ float g_M[C_N * C_N];
__device__ float g_partial[NBLK];
__device__ unsigned int g_ticket;
__device__ unsigned int g_mflag;

__device__ __forceinline__ uint32_t smem_u32(const void* p) {
    uint32_t a;
    asm("{ .reg .u64 t; cvta.to.shared.u64 t, %1; cvt.u32.u64 %0, t; }" : "=r"(a) : "l"(p));
    return a;
}
__device__ __forceinline__ void mbar_init(uint32_t addr, uint32_t cnt) {
    asm volatile("mbarrier.init.shared.b64 [%0], %1;" :: "r"(addr), "r"(cnt) : "memory");
}
__device__ __forceinline__ void mbar_expect_tx(uint32_t addr, uint32_t bytes) {
    asm volatile("mbarrier.arrive.expect_tx.shared.b64 _, [%0], %1;" :: "r"(addr), "r"(bytes) : "memory");
}
__device__ __forceinline__ void mbar_arrive(uint32_t addr) {
    asm volatile("mbarrier.arrive.shared.b64 _, [%0];" :: "r"(addr) : "memory");
}
__device__ __forceinline__ void bulk_g2s(uint32_t dst, const void* src, uint32_t bytes, uint32_t mbar) {
    asm volatile("cp.async.bulk.shared::cta.global.mbarrier::complete_tx::bytes [%0], [%1], %2, [%3];"
                 :: "r"(dst), "l"(src), "r"(bytes), "r"(mbar) : "memory");
}
__device__ __forceinline__ void mbar_wait(uint32_t addr, uint32_t parity) {
    uint32_t done;
    asm volatile(
        "{\n\t.reg .pred p;\n\t"
        "mbarrier.try_wait.parity.shared.b64 p, [%1], %2;\n\t"
        "selp.b32 %0, 1, 0, p;\n\t}"
        : "=r"(done) : "r"(addr), "r"(parity) : "memory");
    if (!done) {
        asm volatile(
            "{\n\t.reg .pred P1;\n\t"
            "WL_%=:\n\t"
            "mbarrier.try_wait.parity.shared.b64 P1, [%0], %1, 0x989680;\n\t"
            "@P1 bra.uni WD_%=;\n\t"
            "bra.uni WL_%=;\n\t"
            "WD_%=:\n\t}"
            :: "r"(addr), "r"(parity) : "memory");
    }
}

// Two rows interleaved: independent FMA blocks then interleaved shfl-reduce chains.
__device__ __forceinline__ void do_rows2(const float2* __restrict__ rowA,
                                         const float2* __restrict__ rowB,
                                         int tid, int warp, int lane,
                                         const ull (&wp)[3][2][5],
                                         float (*sp)[NW][C_N], int rA, int rB) {
    float2 xa0 = rowA[tid], xa1 = rowA[tid + TPB], xa2 = rowA[tid + 2 * TPB];
    float2 xb0 = rowB[tid], xb1 = rowB[tid + TPB], xb2 = rowB[tid + 2 * TPB];

    ull accA[5], accB[5];
#pragma unroll
    for (int m = 0; m < 5; m++) { accA[m] = 0ull; accB[m] = 0ull; }

#pragma unroll
    for (int j = 0; j < 3; j++)
#pragma unroll
        for (int c2 = 0; c2 < 2; c2++) {
            float xva = (j == 0) ? (c2 == 0 ? xa0.x : xa0.y)
                      : (j == 1) ? (c2 == 0 ? xa1.x : xa1.y)
                                 : (c2 == 0 ? xa2.x : xa2.y);
            float xvb = (j == 0) ? (c2 == 0 ? xb0.x : xb0.y)
                      : (j == 1) ? (c2 == 0 ? xb1.x : xb1.y)
                                 : (c2 == 0 ? xb2.x : xb2.y);
            ull xba, xbb;
            asm("mov.b64 %0, {%1, %1};" : "=l"(xba) : "f"(xva));
            asm("mov.b64 %0, {%1, %1};" : "=l"(xbb) : "f"(xvb));
#pragma unroll
            for (int m = 0; m < 5; m++) {
                asm("fma.rn.f32x2 %0, %1, %2, %0;"
                    : "+l"(accA[m]) : "l"(xba), "l"(wp[j][c2][m]));
                asm("fma.rn.f32x2 %0, %1, %2, %0;"
                    : "+l"(accB[m]) : "l"(xbb), "l"(wp[j][c2][m]));
            }
        }

    float zA[C_N], zB[C_N];
#pragma unroll
    for (int m = 0; m < 5; m++) {
        asm("mov.b64 {%0, %1}, %2;" : "=f"(zA[2*m]), "=f"(zA[2*m+1]) : "l"(accA[m]));
        asm("mov.b64 {%0, %1}, %2;" : "=f"(zB[2*m]), "=f"(zB[2*m+1]) : "l"(accB[m]));
    }

    const bool hi16 = (lane & 16) != 0;
    const bool hi8  = (lane & 8) != 0;
    float vA[5], vB[5];
#pragma unroll
    for (int j = 0; j < 5; j++) {
        float sA = hi16 ? zA[j] : zA[j + 5];
        float sB = hi16 ? zB[j] : zB[j + 5];
        float oA = __shfl_xor_sync(0xffffffffu, sA, 16);
        float oB = __shfl_xor_sync(0xffffffffu, sB, 16);
        vA[j] = (hi16 ? zA[j + 5] : zA[j]) + oA;
        vB[j] = (hi16 ? zB[j + 5] : zB[j]) + oB;
    }
    float uA[3], uB[3];
#pragma unroll
    for (int j = 0; j < 3; j++) {
        float mA = (j < 2) ? vA[j + 3] : 0.f;
        float mB = (j < 2) ? vB[j + 3] : 0.f;
        float sA = hi8 ? vA[j] : mA;
        float sB = hi8 ? vB[j] : mB;
        float oA = __shfl_xor_sync(0xffffffffu, sA, 8);
        float oB = __shfl_xor_sync(0xffffffffu, sB, 8);
        uA[j] = (hi8 ? mA : vA[j]) + oA;
        uB[j] = (hi8 ? mB : vB[j]) + oB;
    }
#pragma unroll
    for (int off = 4; off; off >>= 1)
#pragma unroll
        for (int j = 0; j < 3; j++) {
            uA[j] += __shfl_xor_sync(0xffffffffu, uA[j], off);
            uB[j] += __shfl_xor_sync(0xffffffffu, uB[j], off);
        }

    if ((lane & 7) == 0) {
        int vb = (hi16 ? 5 : 0) + (hi8 ? 3 : 0);
        int c = hi8 ? 2 : 3;
#pragma unroll
        for (int j = 0; j < 3; j++)
            if (j < c) {
                sp[rA][warp][vb + j] = uA[j];
                sp[rB][warp][vb + j] = uB[j];
            }
    }
}

// Single row (tails).
__device__ __forceinline__ void do_row(const float2* __restrict__ row, int tid, int warp, int lane,
                                       const ull (&wp)[3][2][5],
                                       float (*sp)[NW][C_N], int r) {
    float2 x0 = row[tid], x1 = row[tid + TPB], x2 = row[tid + 2 * TPB];
    ull acc[5];
#pragma unroll
    for (int m = 0; m < 5; m++) acc[m] = 0ull;
#pragma unroll
    for (int j = 0; j < 3; j++)
#pragma unroll
        for (int c2 = 0; c2 < 2; c2++) {
            float xv = (j == 0) ? (c2 == 0 ? x0.x : x0.y)
                     : (j == 1) ? (c2 == 0 ? x1.x : x1.y)
                                : (c2 == 0 ? x2.x : x2.y);
            ull xb;
            asm("mov.b64 %0, {%1, %1};" : "=l"(xb) : "f"(xv));
#pragma unroll
            for (int m = 0; m < 5; m++)
                asm("fma.rn.f32x2 %0, %1, %2, %0;"
                    : "+l"(acc[m]) : "l"(xb), "l"(wp[j][c2][m]));
        }
    float z[C_N];
#pragma unroll
    for (int m = 0; m < 5; m++)
        asm("mov.b64 {%0, %1}, %2;" : "=f"(z[2*m]), "=f"(z[2*m+1]) : "l"(acc[m]));

    const bool hi16 = (lane & 16) != 0;
    const bool hi8  = (lane & 8) != 0;
    float v[5];
#pragma unroll
    for (int j = 0; j < 5; j++) {
        float send = hi16 ? z[j] : z[j + 5];
        float oth = __shfl_xor_sync(0xffffffffu, send, 16);
        v[j] = (hi16 ? z[j + 5] : z[j]) + oth;
    }
    float u[3];
#pragma unroll
    for (int j = 0; j < 3; j++) {
        float mine = (j < 2) ? v[j + 3] : 0.f;
        float send = hi8 ? v[j] : mine;
        float oth = __shfl_xor_sync(0xffffffffu, send, 8);
        u[j] = (hi8 ? mine : v[j]) + oth;
    }
#pragma unroll
    for (int off = 4; off; off >>= 1)
#pragma unroll
        for (int j = 0; j < 3; j++)
            u[j] += __shfl_xor_sync(0xffffffffu, u[j], off);

    if ((lane & 7) == 0) {
        int vb = (hi16 ? 5 : 0) + (hi8 ? 3 : 0);
        int c = hi8 ? 2 : 3;
#pragma unroll
        for (int j = 0; j < 3; j++)
            if (j < c) sp[r][warp][vb + j] = u[j];
    }
}

__global__ void __launch_bounds__(TPB, 1) jacreg_kernel(
        const float* __restrict__ X, const float* __restrict__ W,
        float* __restrict__ out) {
    extern __shared__ float tiles[];
    __shared__ float sM[C_N * C_N];
    __shared__ float sp[MAXR][NW][C_N];
    __shared__ float redM[NW][56];
    __shared__ ull mb_full[STG];
    __shared__ ull mb_cons[STG];
    __shared__ int slast;

    const int tid = threadIdx.x, b = blockIdx.x;
    const int warp = tid >> 5, lane = tid & 31;
    int r0, r1;
    if (b == 0) { r0 = 0; r1 = R0BLK; }
    else {
        r0 = R0BLK + (int)(((long long)(b - 1) * REMROWS) / NB1);
        r1 = R0BLK + (int)(((long long)b * REMROWS) / NB1);
    }
    const int nrows = r1 - r0;
    const int ntiles = (nrows + RPT - 1) / RPT;

    // W packed into f32x2 class-pairs: thread owns 6 D-positions e = (j*TPB+tid)*2+c2
    ull wp[3][2][5];
#pragma unroll
    for (int j = 0; j < 3; j++)
#pragma unroll
        for (int c2 = 0; c2 < 2; c2++) {
            int e = (j * TPB + tid) * 2 + c2;
            const ull* wrow = (const ull*)(W + (size_t)e * C_N);
#pragma unroll
            for (int m = 0; m < 5; m++) wp[j][c2][m] = wrow[m];
        }

    uint32_t full_a = smem_u32(&mb_full[0]);
    uint32_t cons_a = smem_u32(&mb_cons[0]);
    uint32_t tile_a = smem_u32(&tiles[0]);

    if (tid == 0) {
#pragma unroll
        for (int s = 0; s < STG; s++) {
            mbar_init(full_a + 8 * s, 1);
            mbar_init(cons_a + 8 * s, NW);
        }
        asm volatile("fence.proxy.async.shared::cta;" ::: "memory");
    }
    __syncthreads();

    // Prologue: fill all stages
    if (tid == 0) {
        int np = (ntiles < STG) ? ntiles : STG;
        for (int t = 0; t < np; t++) {
            int rbase = t * RPT;
            int cnt = nrows - rbase; if (cnt > RPT) cnt = RPT;
            uint32_t bytes = (uint32_t)cnt * D_N * 4;
            mbar_expect_tx(full_a + 8 * t, bytes);
            bulk_g2s(tile_a + t * TILE_BYTES,
                     X + (size_t)(r0 + rbase) * D_N, bytes, full_a + 8 * t);
        }
    }

    // Block 0: M = W^T W from wp registers; publish with release flag
    if (b == 0) {
        float w[6][C_N];
#pragma unroll
        for (int j = 0; j < 3; j++)
#pragma unroll
            for (int c2 = 0; c2 < 2; c2++)
#pragma unroll
                for (int m = 0; m < 5; m++)
                    asm("mov.b64 {%0, %1}, %2;"
                        : "=f"(w[j * 2 + c2][2 * m]), "=f"(w[j * 2 + c2][2 * m + 1])
                        : "l"(wp[j][c2][m]));
        int idx = 0;
#pragma unroll
        for (int k = 0; k < C_N; k++) {
            float a[C_N];
#pragma unroll
            for (int l = k; l < C_N; l++) {
                float s = 0.f;
#pragma unroll
                for (int pos = 0; pos < 6; pos++) s += w[pos][k] * w[pos][l];
                a[l - k] = s;
            }
#pragma unroll
            for (int off = 16; off; off >>= 1)
#pragma unroll
                for (int t = 0; t < C_N - k; t++)
                    a[t] += __shfl_xor_sync(0xffffffffu, a[t], off);
            if (lane == 0)
#pragma unroll
                for (int t = 0; t < C_N - k; t++) redM[warp][idx + t] = a[t];
            idx += C_N - k;
        }
        __syncthreads();
        if (tid < 55) {
            float s = 0.f;
#pragma unroll
            for (int wv = 0; wv < NW; wv++) s += redM[wv][tid];
            int k = 0, t = tid;
            while (t >= C_N - k) { t -= C_N - k; k++; }
            int l = k + t;
            g_M[k * C_N + l] = s;
            g_M[l * C_N + k] = s;
        }
        __syncthreads();
        if (tid == 0) {
            __threadfence();
            *(volatile unsigned int*)&g_mflag = 1u;
        }
    }

    // -------- Phase A: producer-consumer, paired rows for 2x ILP --------
    for (int t = 0; t < ntiles; t++) {
        int s = t % STG;
        uint32_t par = (t / STG) & 1;
        mbar_wait(full_a + 8 * s, par);

        int rbase = t * RPT;
        int cnt = nrows - rbase; if (cnt > RPT) cnt = RPT;
        const float2* tile = (const float2*)(tiles + s * TILE_FLOATS);

        int rl = 0;
        for (; rl + 1 < cnt; rl += 2)
            do_rows2(tile + rl * (D_N / 2), tile + (rl + 1) * (D_N / 2),
                     tid, warp, lane, wp, sp, rbase + rl, rbase + rl + 1);
        if (rl < cnt)
            do_row(tile + rl * (D_N / 2), tid, warp, lane, wp, sp, rbase + rl);

        if (lane == 0) mbar_arrive(cons_a + 8 * s);

        if (warp == 0) {
            int tt = t + STG;
            if (tt < ntiles) {
                mbar_wait(cons_a + 8 * s, par);
                if (lane == 0) {
                    int rb = tt * RPT;
                    int c = nrows - rb; if (c > RPT) c = RPT;
                    uint32_t bytes = (uint32_t)c * D_N * 4;
                    mbar_expect_tx(full_a + 8 * s, bytes);
                    bulk_g2s(tile_a + s * TILE_BYTES,
                             X + (size_t)(r0 + rb) * D_N, bytes, full_a + 8 * s);
                }
            }
        }
    }

    // Acquire M (block0 published long ago)
    if (tid == 0) {
        volatile unsigned int* vf = &g_mflag;
        while (*vf == 0u) {}
        __threadfence();
    }
    __syncthreads();
    if (tid < C_N * C_N) sM[tid] = g_M[tid];
    __syncthreads();

    // -------- Phase B: one thread per row --------
    float myreg = 0.f;
    if (tid < nrows) {
        float z[C_N];
#pragma unroll
        for (int k = 0; k < C_N; k++) {
            float s = 0.f;
#pragma unroll
            for (int wv = 0; wv < NW; wv++) s += sp[tid][wv][k];
            z[k] = s;
        }
        float zmax = z[0];
#pragma unroll
        for (int k = 1; k < C_N; k++) zmax = fmaxf(zmax, z[k]);
        float q[C_N], qs = 0.f;
#pragma unroll
        for (int k = 0; k < C_N; k++) { q[k] = __expf(z[k] - zmax); qs += q[k]; }
        float inv = 1.f / qs;
#pragma unroll
        for (int k = 0; k < C_N; k++) q[k] *= inv;

        const float A = 1.0f - (float)C_N * 1e-6f;
        float p[C_N], sq[C_N];
#pragma unroll
        for (int k = 0; k < C_N; k++) { p[k] = q[k] * A + 1e-6f; sq[k] = sqrtf(p[k]); }
        float sm = sq[C_N - 1], qm = q[C_N - 1];
        float om = 1.f - sm;

        float uu[C_N], Qf = 0.f;
#pragma unroll
        for (int k = 0; k < C_N; k++) {
            float t = 0.f;
#pragma unroll
            for (int l = 0; l < C_N; l++) t += sM[k * C_N + l] * q[l];
            uu[k] = t;
            Qf += q[k] * t;
        }

        float jac2 = 0.f;
        float bfac = A * qm / (sm * om * om);
#pragma unroll
        for (int i = 0; i < C_N - 1; i++) {
            float al = A * q[i] / (sq[i] * om);
            float be = sq[i] * bfac;
            float ga = al + be;
            jac2 += al * al * sM[i * C_N + i]
                  + be * be * sM[C_N * C_N - 1]
                  + ga * ga * Qf
                  + 2.f * al * be * sM[i * C_N + (C_N - 1)]
                  - 2.f * al * ga * uu[i]
                  - 2.f * be * ga * uu[C_N - 1];
        }
        float jn = sqrtf(jac2);

        float ssum = 0.f;
#pragma unroll
        for (int k = 0; k < C_N; k++) ssum += sq[k];
        float arg = ssum * 0.316227766016838f;
        arg = fminf(fmaxf(arg, -1.f), 1.f);
        float delta = 2.f * acosf(arg);

        float psum = 0.f;
#pragma unroll
        for (int k = 0; k < C_N - 1; k++) psum += p[k];
        float rho = (2.f * om - psum) / om;

        float xv = jn - delta / (rho * 0.1f);
        myreg = (xv > 0.f) ? xv : expm1f(xv);
    }

    if (warp == 0) {
#pragma unroll
        for (int off = 16; off; off >>= 1)
            myreg += __shfl_xor_sync(0xffffffffu, myreg, off);
        if (lane == 0) {
            g_partial[b] = myreg;
            __threadfence();
            unsigned int rank = atomicAdd(&g_ticket, 1u);
            slast = (rank == NBLK - 1) ? 1 : 0;
            if (rank == NBLK - 1) {
                g_ticket = 0u;
                g_mflag = 0u;
            }
        }
    }
    __syncthreads();

    if (slast && warp == 0) {
        float s = 0.f;
        for (int i = lane; i < NBLK; i += 32) s += __ldcg(&g_partial[i]);
#pragma unroll
        for (int off = 16; off; off >>= 1)
            s += __shfl_xor_sync(0xffffffffu, s, off);
        if (lane == 0) out[0] = s * (1.f / (float)B_N);
    }
}

extern "C" void kernel_launch(void* const* d_in, const int* in_sizes, int n_in,
                              void* d_out, int out_size) {
    const float* X = (const float*)d_in[0];
    const float* W = (const float*)d_in[1];
    float* out = (float*)d_out;
    cudaFuncSetAttribute(jacreg_kernel,
                         cudaFuncAttributeMaxDynamicSharedMemorySize, DYN_SMEM);
    jacreg_kernel<<<NBLK, TPB, DYN_SMEM>>>(X, W, out);
}